// round 3
// baseline (speedup 1.0000x reference)
#include <cuda_runtime.h>
#include <cuda_fp16.h>
#include <cuda_bf16.h>

// TokenAwareEmbedding: per-token NF4 dequant + special-token override.
// Device dtypes are auto-detected (harness narrows int64->int32 and maps
// fp16 to bf16 or fp32; we classify at runtime).
//   0: input_ids          int32|int64 [8, 2048]
//   1: main_quantized     int32       [804112, 64]
//   2: main_scales        fp32        [804112]
//   3: special_embeddings fp32|fp16|bf16 [256, 1024]
//   4: special_indices    int32|int64 [256] (sorted)
// output: fp32 [8, 2048, 1024]

#define VOCAB 50257
#define DIM 1024
#define NTOK (8 * 2048)
#define NSPEC 256

__constant__ float c_nf4[16] = {
    -1.0f, -0.6962f, -0.5251f, -0.3949f, -0.2844f, -0.1848f, -0.0911f, 0.0f,
    0.0796f, 0.1609f, 0.2461f, 0.3379f, 0.4407f, 0.5626f, 0.723f, 1.0f};

// g_flags[0] = index width (1 = int64, 0 = int32)
// g_flags[1] = spec dtype  (0 = fp32, 1 = fp16, 2 = bf16)
__device__ int g_flags[2];

__device__ __forceinline__ float finite_abs(float v) {
    return isfinite(v) ? fabsf(v) : 1e30f;
}

__global__ void detect_kernel(const int* __restrict__ ids32,
                              const unsigned short* __restrict__ specu) {
    __shared__ float s_sum[3][8];
    __shared__ float s_max[3][8];
    const int tid = threadIdx.x;
    float sum[3] = {0.f, 0.f, 0.f};
    float mx[3] = {0.f, 0.f, 0.f};
    #pragma unroll
    for (int k = 0; k < 4; k++) {
        int i = tid * 4 + k;  // first 1024 elements
        float vh = finite_abs(__half2float(((const __half*)specu)[i]));
        float vb = finite_abs(__bfloat162float(((const __nv_bfloat16*)specu)[i]));
        float vf = finite_abs(((const float*)specu)[i]);
        sum[0] += vh; mx[0] = fmaxf(mx[0], vh);
        sum[1] += vb; mx[1] = fmaxf(mx[1], vb);
        sum[2] += vf; mx[2] = fmaxf(mx[2], vf);
    }
    #pragma unroll
    for (int c = 0; c < 3; c++) {
        #pragma unroll
        for (int o = 16; o > 0; o >>= 1) {
            sum[c] += __shfl_down_sync(0xFFFFFFFFu, sum[c], o);
            mx[c] = fmaxf(mx[c], __shfl_down_sync(0xFFFFFFFFu, mx[c], o));
        }
        if ((tid & 31) == 0) { s_sum[c][tid >> 5] = sum[c]; s_max[c][tid >> 5] = mx[c]; }
    }
    __syncthreads();
    if (tid == 0) {
        float S[3], M[3];
        #pragma unroll
        for (int c = 0; c < 3; c++) {
            S[c] = 0.f; M[c] = 0.f;
            #pragma unroll
            for (int w = 0; w < 8; w++) { S[c] += s_sum[c][w]; M[c] = fmaxf(M[c], s_max[c][w]); }
            S[c] *= (1.0f / 1024.0f);  // mean |x|; N(0,1) -> ~0.798
        }
        int dt;
        if (M[0] < 10.f && fabsf(S[0] - 0.8f) < 0.3f)      dt = 1;  // fp16
        else if (M[1] < 10.f && fabsf(S[1] - 0.8f) < 0.3f) dt = 2;  // bf16
        else                                                dt = 0;  // fp32
        g_flags[1] = dt;

        // index width: int64 values < 2^31 have zero odd int32 words
        bool wide = true;
        #pragma unroll
        for (int k = 1; k < 64; k += 2) wide &= (ids32[k] == 0);
        g_flags[0] = wide ? 1 : 0;
    }
}

__device__ __forceinline__ long long load_idx(const void* p, int i, bool wide) {
    if (wide) return ((const long long*)p)[i];
    return (long long)((const int*)p)[i];
}

__global__ __launch_bounds__(256)
void tok_embed_kernel(const void* __restrict__ ids,
                      const int* __restrict__ quant,
                      const float* __restrict__ scales,
                      const unsigned short* __restrict__ specu,
                      const void* __restrict__ sidx,
                      float* __restrict__ out) {
    const int tok = blockIdx.x;

    __shared__ int s_row;
    __shared__ long long s_t;
    __shared__ int s_dt;
    if (threadIdx.x == 0) {
        const bool wide = (g_flags[0] != 0);
        s_dt = g_flags[1];

        long long t = load_idx(ids, tok, wide);
        if (t < 0) t = 0;
        if (t >= VOCAB) t = VOCAB - 1;
        s_t = t;

        // upper_bound over sorted special_indices; last-wins for duplicates
        int lo = 0, hi = NSPEC;
        while (lo < hi) {
            int mid = (lo + hi) >> 1;
            if (load_idx(sidx, mid, wide) <= t) lo = mid + 1; else hi = mid;
        }
        s_row = (lo > 0 && load_idx(sidx, lo - 1, wide) == t) ? (lo - 1) : -1;
    }
    __syncthreads();
    const int r = s_row;
    const long long t = s_t;

    const int d = threadIdx.x * 4;  // 4 consecutive dims per thread
    float4 o;
    if (r >= 0) {
        const size_t base = (size_t)r * DIM + d;
        const int dt = s_dt;
        if (dt == 0) {
            o = *reinterpret_cast<const float4*>((const float*)specu + base);
        } else if (dt == 1) {
            const __half2* sp = reinterpret_cast<const __half2*>((const __half*)specu + base);
            float2 fa = __half22float2(sp[0]);
            float2 fb = __half22float2(sp[1]);
            o = make_float4(fa.x, fa.y, fb.x, fb.y);
        } else {
            const __nv_bfloat162* sp =
                reinterpret_cast<const __nv_bfloat162*>((const __nv_bfloat16*)specu + base);
            float2 fa = __bfloat1622float2(sp[0]);
            float2 fb = __bfloat1622float2(sp[1]);
            o = make_float4(fa.x, fa.y, fb.x, fb.y);
        }
    } else {
        const int4 qi = *reinterpret_cast<const int4*>(quant + (size_t)t * DIM + d);
        const float s = __ldg(scales + (size_t)t * (DIM / 64) + (d >> 6));
        o = make_float4(c_nf4[qi.x & 15] * s, c_nf4[qi.y & 15] * s,
                        c_nf4[qi.z & 15] * s, c_nf4[qi.w & 15] * s);
    }
    *reinterpret_cast<float4*>(out + (size_t)tok * DIM + d) = o;
}

extern "C" void kernel_launch(void* const* d_in, const int* in_sizes, int n_in,
                              void* d_out, int out_size) {
    const void*  ids    = d_in[0];
    const int*   quant  = (const int*)d_in[1];
    const float* scales = (const float*)d_in[2];
    const unsigned short* spec = (const unsigned short*)d_in[3];
    const void*  sidx   = d_in[4];
    float* out = (float*)d_out;

    detect_kernel<<<1, 256>>>((const int*)ids, spec);
    tok_embed_kernel<<<NTOK, 256>>>(ids, quant, scales, spec, sidx, out);
}